// round 15
// baseline (speedup 1.0000x reference)
#include <cuda_runtime.h>
#include <cuda_fp16.h>
#include <stdint.h>

// Problem constants
#define BB   16
#define CIN  1024
#define TT   2000
#define BNC  512
#define OUTC 512
#define NBR  3
#define FSZ  (BB * OUTC * TT)

// Fragment-native branch-output layout:
//   word = [b][oy(4)][tx(21)][warp(12)][mg(2)][t8(2)][n8(4)][lane(32)]
#define FBRW 8257536L     // 16*4*21*12*512 words per branch

// ---------------------------------------------------------------------------
// Device scratch (fp16 pairs in uint32)
// ---------------------------------------------------------------------------
__device__ uint32_t g_xi[(long)BB * TT * 64 * 8];      // 65.5 MB
__device__ uint32_t g_h2i[(long)BB * TT * 32 * 8];     // 32.7 MB
__device__ uint32_t g_w1p[64 * 512 * 8];               // 1 MB
__device__ uint32_t g_wcp[9 * 32 * 512 * 8];           // 4.7 MB
__device__ uint32_t g_fh[3L * FBRW];                   // 99 MB fragment-native
__device__ float g_mom[4 * BB * OUTC];
__device__ float g_stats[BB * 4 * OUTC];
__device__ float g_s[BB * NBR * OUTC];
__device__ float g_a1[CIN], g_b1[CIN], g_a2[BNC], g_b2[BNC];

// ---------------------------------------------------------------------------
__device__ __forceinline__ uint32_t pack2h(__half a, __half b) {
    return (uint32_t)__half_as_ushort(a) | ((uint32_t)__half_as_ushort(b) << 16);
}
__device__ __forceinline__ void mma16816h(float* d, const uint32_t* a, const uint32_t* b) {
    asm volatile(
        "mma.sync.aligned.m16n8k16.row.col.f32.f16.f16.f32 "
        "{%0,%1,%2,%3}, {%4,%5,%6,%7}, {%8,%9}, {%0,%1,%2,%3};\n"
        : "+f"(d[0]), "+f"(d[1]), "+f"(d[2]), "+f"(d[3])
        : "r"(a[0]), "r"(a[1]), "r"(a[2]), "r"(a[3]), "r"(b[0]), "r"(b[1]));
}
__device__ __forceinline__ void ldsm4(uint32_t* r, uint32_t addr) {
    asm volatile("ldmatrix.sync.aligned.m8n8.x4.shared.b16 {%0,%1,%2,%3}, [%4];"
                 : "=r"(r[0]), "=r"(r[1]), "=r"(r[2]), "=r"(r[3]) : "r"(addr));
}
__device__ __forceinline__ uint32_t saddr(const void* p) {
    return (uint32_t)__cvta_generic_to_shared(p);
}
__device__ __forceinline__ void cpasync16(uint32_t dst, const void* src, int szbytes) {
    asm volatile("cp.async.cg.shared.global [%0], [%1], 16, %2;\n"
                 :: "r"(dst), "l"(src), "r"(szbytes));
}
#define CP_COMMIT() asm volatile("cp.async.commit_group;\n" ::: "memory")
#define CP_WAIT1()  asm volatile("cp.async.wait_group 1;\n" ::: "memory")
#define CP_WAIT0()  asm volatile("cp.async.wait_group 0;\n" ::: "memory")

// ---------------------------------------------------------------------------
// Kernel: fold BN params + zero moment accumulators
// ---------------------------------------------------------------------------
__global__ void prep_bn_kernel(const float* __restrict__ g1, const float* __restrict__ be1,
                               const float* __restrict__ m1, const float* __restrict__ v1,
                               const float* __restrict__ g2, const float* __restrict__ be2,
                               const float* __restrict__ m2, const float* __restrict__ v2)
{
    int i = threadIdx.x;
    if (i < CIN) {
        float inv = g1[i] * rsqrtf(v1[i] + 1e-5f);
        g_a1[i] = inv;
        g_b1[i] = be1[i] - m1[i] * inv;
    }
    if (i < BNC) {
        float inv = g2[i] * rsqrtf(v2[i] + 1e-5f);
        g_a2[i] = inv;
        g_b2[i] = be2[i] - m2[i] * inv;
    }
    for (int j = i; j < 4 * BB * OUTC; j += 1024) g_mom[j] = 0.f;
}

// ---------------------------------------------------------------------------
// Kernel: fp16 W1 -> g_w1p  [ch][o][8 words]
// ---------------------------------------------------------------------------
__global__ void prep_w1_kernel(const float* __restrict__ W1)
{
    int idx = blockIdx.x * 256 + threadIdx.x;
    if (idx >= 512 * 512) return;
    int o  = idx >> 9;
    int c2 = idx & 511;
    float w0 = W1[o * CIN + 2 * c2];
    float w1 = W1[o * CIN + 2 * c2 + 1];
    g_w1p[((long)(c2 >> 3) * 512 + o) * 8 + (c2 & 7)] =
        pack2h(__float2half_rn(w0), __float2half_rn(w1));
}

// ---------------------------------------------------------------------------
// Kernel: fp16 conv_w -> g_wcp  [comb][ch][o][8 words].  conv_w: [i][o][c][k]
// ---------------------------------------------------------------------------
__global__ void prep_wc_kernel(const float* __restrict__ conv_w)
{
    int idx = blockIdx.x * 256 + threadIdx.x;
    if (idx >= 9 * 512 * 256) return;
    int comb = idx / (512 * 256);
    int r = idx - comb * (512 * 256);
    int o  = r >> 8;
    int c2 = r & 255;
    int i = comb / 3, k = comb % 3;
    int c = 2 * c2;
    float w0 = conv_w[(((long)i * 512 + o) * 512 + c) * 3 + k];
    float w1 = conv_w[(((long)i * 512 + o) * 512 + c + 1) * 3 + k];
    g_wcp[(((long)comb * 32 + (c2 >> 3)) * 512 + o) * 8 + (c2 & 7)] =
        pack2h(__float2half_rn(w0), __float2half_rn(w1));
}

// ---------------------------------------------------------------------------
// Kernel: prep_x -- bn1+relu, round to fp16, into g_xi (smem transpose)
// ---------------------------------------------------------------------------
__global__ __launch_bounds__(256)
void prep_x_kernel(const float* __restrict__ x)
{
    __shared__ float sm[32 * 132];
    const int c0 = blockIdx.x * 32;
    const int t0 = blockIdx.y * 128;
    const int b  = blockIdx.z;
    const int tid = threadIdx.x;

    for (int i = tid; i < 1024; i += 256) {
        int c = i >> 5, t4 = i & 31;
        int t = t0 + t4 * 4;
        float4 v = make_float4(0.f, 0.f, 0.f, 0.f);
        if (t < TT) v = *reinterpret_cast<const float4*>(&x[((long)(b * CIN + c0 + c)) * TT + t]);
        *reinterpret_cast<float4*>(&sm[c * 132 + t4 * 4]) = v;
    }
    __syncthreads();

    for (int i = tid; i < 512; i += 256) {
        int t   = i >> 2;
        int ch2 = (i >> 1) & 1;
        int q   = i & 1;
        if (t0 + t >= TT) continue;
        uint32_t w[4];
        #pragma unroll
        for (int j = 0; j < 4; j++) {
            int c = ch2 * 16 + q * 8 + 2 * j;
            int cg = c0 + c;
            float v0 = fmaxf(fmaf(sm[c * 132 + t],       g_a1[cg],     g_b1[cg]),     0.f);
            float v1 = fmaxf(fmaf(sm[(c + 1) * 132 + t], g_a1[cg + 1], g_b1[cg + 1]), 0.f);
            w[j] = pack2h(__float2half_rn(v0), __float2half_rn(v1));
        }
        long widx = (((long)b * TT + t0 + t) * 64 + (c0 >> 4) + ch2) * 8 + q * 4;
        *reinterpret_cast<uint4*>(&g_xi[widx]) = make_uint4(w[0], w[1], w[2], w[3]);
    }
}

// ---------------------------------------------------------------------------
// GEMM: h2 = relu(bn2(W1 @ xbn)).  Pure fp16 MMA, 2-stage cp.async.
// Block 128t x 128o, 256 threads (8 warps: 4t x 2o), warp 32t x 64o.
// ---------------------------------------------------------------------------
__global__ __launch_bounds__(256, 2)
void gemm_mma_kernel()
{
    __shared__ uint32_t As[2][128 * 12];
    __shared__ uint32_t Bs[2][128 * 12];
    __shared__ float bn2s[256];

    const int t0 = blockIdx.x * 128;
    const int om = blockIdx.y * 128;
    const int b  = blockIdx.z;

    const int tid  = threadIdx.x;
    const int warp = tid >> 5, lane = tid & 31;
    const int wt = warp >> 1, wo = warp & 1;

    if (tid < 128) {
        bn2s[tid]       = g_a2[om + tid];
        bn2s[128 + tid] = g_b2[om + tid];
    }

    float acc[2][8][4];
    #pragma unroll
    for (int m = 0; m < 2; m++)
        #pragma unroll
        for (int n = 0; n < 8; n++)
            #pragma unroll
            for (int j = 0; j < 4; j++) acc[m][n][j] = 0.f;

    const uint32_t as_base = saddr(As), bs_base = saddr(Bs);
    const int lrA = lane & 15, lwA = ((lane >> 4) & 1) * 4;
    uint32_t aA[2];
    #pragma unroll
    for (int mt = 0; mt < 2; mt++) {
        uint32_t r = (uint32_t)(wt * 32 + mt * 16 + lrA);
        aA[mt] = as_base + (r * 12 + lwA) * 4;
    }
    const int rB = ((lane >> 4) & 1) * 8 + (lane & 7);
    const int wB = ((lane >> 3) & 1) * 4;
    uint32_t aB[4];
    #pragma unroll
    for (int g = 0; g < 4; g++) {
        uint32_t r = (uint32_t)(wo * 64 + g * 16 + rB);
        aB[g] = bs_base + (r * 12 + wB) * 4;
    }

    auto fill = [&](int st, int ch) {
        {
            int r = tid >> 1, q = tid & 1;
            int t = t0 + r;
            int ok = (t < TT);
            const void* gp = &g_xi[(((long)b * TT + (ok ? t : 0)) * 64 + ch) * 8 + q * 4];
            cpasync16(as_base + (uint32_t)st * 6144 + (r * 12 + q * 4) * 4, gp, ok ? 16 : 0);
        }
        {
            int r = tid >> 1, q = tid & 1;
            const void* gp = &g_w1p[((long)ch * 512 + om + r) * 8 + q * 4];
            cpasync16(bs_base + (uint32_t)st * 6144 + (r * 12 + q * 4) * 4, gp, 16);
        }
    };

    fill(0, 0);
    CP_COMMIT();

    for (int ch = 0; ch < 64; ch++) {
        int st = ch & 1;
        if (ch + 1 < 64) {
            fill(st ^ 1, ch + 1);
            CP_COMMIT();
            CP_WAIT1();
        } else {
            CP_WAIT0();
        }
        __syncthreads();

        uint32_t soff = (uint32_t)st * 6144;
        uint32_t ah[2][4];
        ldsm4(ah[0], aA[0] + soff);
        ldsm4(ah[1], aA[1] + soff);

        #pragma unroll
        for (int g = 0; g < 4; g++) {
            uint32_t bh[4];
            ldsm4(bh, aB[g] + soff);
            #pragma unroll
            for (int mt = 0; mt < 2; mt++) {
                mma16816h(acc[mt][2 * g],     ah[mt], &bh[0]);
                mma16816h(acc[mt][2 * g + 1], ah[mt], &bh[2]);
            }
        }
        __syncthreads();
    }

    // epilogue: bn2+relu, round to fp16, store g_h2i
    #pragma unroll
    for (int mt = 0; mt < 2; mt++) {
        #pragma unroll
        for (int hf = 0; hf < 2; hf++) {
            int t = t0 + wt * 32 + mt * 16 + (lane >> 2) + hf * 8;
            if (t >= TT) continue;
            long tb = ((long)b * TT + t) * 256;
            #pragma unroll
            for (int n8 = 0; n8 < 8; n8++) {
                int ol = wo * 64 + n8 * 8 + 2 * (lane & 3);
                float v0 = fmaxf(fmaf(acc[mt][n8][hf * 2],     bn2s[ol],     bn2s[128 + ol]), 0.f);
                float v1 = fmaxf(fmaf(acc[mt][n8][hf * 2 + 1], bn2s[ol + 1], bn2s[129 + ol]), 0.f);
                int o = om + ol;
                g_h2i[tb + (long)(o >> 4) * 8 + ((o & 15) >> 1)] =
                    pack2h(__float2half_rn(v0), __float2half_rn(v1));
            }
        }
    }
}

// ---------------------------------------------------------------------------
// Conv: 3-branch dilated conv, pure fp16 MMA, 2-stage cp.async.
// Block 96t x 128o, 384 threads (12 warps: 3t x 4o), warp 32t x 32o.
// Epilogue A: direct register stores to fragment-native g_fh.
// Epilogue B: branch-sum raw moments (shfl + atomics), OOB-t PREDICATED.
// ---------------------------------------------------------------------------
#define CSTG_WORDS 15048
#define CSM_BYTES  (2 * CSTG_WORDS * 4)

__global__ __launch_bounds__(384, 1)
void conv_mma_kernel()
{
    extern __shared__ uint32_t cs[];

    const int t0 = blockIdx.x * 96;
    const int om = blockIdx.y * 128;
    const int b  = blockIdx.z;

    const int tid  = threadIdx.x;
    const int warp = tid >> 5, lane = tid & 31;
    const int tsub = (warp >> 2) * 32;   // 0,32,64
    const int osub = (warp & 3) * 32;    // 0,32,64,96

    float acc[3][2][4][4];   // [br][mg][n8][j]
    #pragma unroll
    for (int i = 0; i < 3; i++)
        #pragma unroll
        for (int m = 0; m < 2; m++)
            #pragma unroll
            for (int n = 0; n < 4; n++)
                #pragma unroll
                for (int j = 0; j < 4; j++) acc[i][m][n][j] = 0.f;

    const uint32_t cs_base  = saddr(cs);
    const uint32_t ws_base  = cs_base;
    const uint32_t hsp_base = cs_base + 13824 * 4;
    const int lrA = lane & 15, lwA = ((lane >> 4) & 1) * 4;
    const uint32_t aAbase = hsp_base + ((uint32_t)(tsub + lrA) * 12 + lwA) * 4;
    const int rB = ((lane >> 4) & 1) * 8 + (lane & 7);
    const int wB = ((lane >> 3) & 1) * 4;
    const uint32_t aB0 = ws_base + ((uint32_t)(osub + rB) * 12 + wB) * 4;

    auto fill = [&](int st, int ch) {
        uint32_t sb = (uint32_t)st * (CSTG_WORDS * 4);
        for (int i = tid; i < 2304; i += 384) {
            int comb = i >> 8;
            int r = i & 255;
            int o = r >> 1, q = r & 1;
            const void* gp = &g_wcp[(((long)comb * 32 + ch) * 512 + om + o) * 8 + q * 4];
            cpasync16(ws_base + sb + (uint32_t)(comb * 1536 + o * 12 + q * 4) * 4, gp, 16);
        }
        if (tid < 204) {
            int r = tid >> 1, q = tid & 1;
            int t = t0 - 3 + r;
            int ok = (t >= 0 && t < TT);
            const void* gp = &g_h2i[(((long)b * TT + (ok ? t : 0)) * 32 + ch) * 8 + q * 4];
            cpasync16(hsp_base + sb + (uint32_t)(r * 12 + q * 4) * 4, gp, ok ? 16 : 0);
        }
    };

    auto domma = [&](uint32_t soff, int comb, int br, uint32_t ah[2][4]) {
        #pragma unroll
        for (int g = 0; g < 2; g++) {
            uint32_t bh[4];
            ldsm4(bh, aB0 + soff + (uint32_t)(comb * 6144 + g * 768));
            #pragma unroll
            for (int mg = 0; mg < 2; mg++) {
                mma16816h(acc[br][mg][2 * g],     ah[mg], &bh[0]);
                mma16816h(acc[br][mg][2 * g + 1], ah[mg], &bh[2]);
            }
        }
    };

    fill(0, 0);
    CP_COMMIT();

    for (int ch = 0; ch < 32; ch++) {
        int st = ch & 1;
        if (ch + 1 < 32) {
            fill(st ^ 1, ch + 1);
            CP_COMMIT();
            CP_WAIT1();
        } else {
            CP_WAIT0();
        }
        __syncthreads();

        uint32_t soff = (uint32_t)st * (CSTG_WORDS * 4);
        uint32_t ah[2][4];

        // center taps (doff=3): combs 1,4,7 share A fragments
        {
            #pragma unroll
            for (int mg = 0; mg < 2; mg++)
                ldsm4(ah[mg], aAbase + soff + (uint32_t)(mg * 16 + 3) * 48);
            domma(soff, 1, 0, ah);
            domma(soff, 4, 1, ah);
            domma(soff, 7, 2, ah);
        }
        // off-center taps
        {
            const int combs[6] = {0, 2, 3, 5, 6, 8};
            const int doffs[6] = {2, 4, 1, 5, 0, 6};
            #pragma unroll
            for (int j = 0; j < 6; j++) {
                #pragma unroll
                for (int mg = 0; mg < 2; mg++)
                    ldsm4(ah[mg], aAbase + soff + (uint32_t)(mg * 16 + doffs[j]) * 48);
                domma(soff, combs[j], combs[j] / 3, ah);
            }
        }
        __syncthreads();
    }

    // --- epilogue A: direct fragment-native stores (coalesced, no smem) ---
    const long fbase = ((((long)b * 4 + blockIdx.y) * 21 + blockIdx.x) * 12 + warp) * 512 + lane;
    #pragma unroll
    for (int br = 0; br < 3; br++) {
        long bb2 = fbase + (long)br * FBRW;
        #pragma unroll
        for (int mg = 0; mg < 2; mg++) {
            #pragma unroll
            for (int n8 = 0; n8 < 4; n8++) {
                g_fh[bb2 + mg * 256 + n8 * 32] =
                    pack2h(__float2half_rn(acc[br][mg][n8][0]),
                           __float2half_rn(acc[br][mg][n8][1]));
                g_fh[bb2 + mg * 256 + 128 + n8 * 32] =
                    pack2h(__float2half_rn(acc[br][mg][n8][2]),
                           __float2half_rn(acc[br][mg][n8][3]));
            }
        }
    }

    // --- epilogue B: branch-sum raw moments, OOB-t predicated ---
    // thread's t for (mg, tt): t0 + tsub + mg*16 + (lane>>2) + tt*8
    float tw[2][2];
    #pragma unroll
    for (int mg = 0; mg < 2; mg++)
        #pragma unroll
        for (int tt = 0; tt < 2; tt++)
            tw[mg][tt] = (t0 + tsub + mg * 16 + (lane >> 2) + tt * 8 < TT) ? 1.f : 0.f;

    #pragma unroll
    for (int n8 = 0; n8 < 4; n8++) {
        #pragma unroll
        for (int hf = 0; hf < 2; hf++) {
            float s1 = 0.f, s2 = 0.f, s3 = 0.f, s4 = 0.f;
            #pragma unroll
            for (int mg = 0; mg < 2; mg++) {
                #pragma unroll
                for (int tt = 0; tt < 2; tt++) {
                    float v = (acc[0][mg][n8][hf + 2 * tt] +
                               acc[1][mg][n8][hf + 2 * tt] +
                               acc[2][mg][n8][hf + 2 * tt]) * tw[mg][tt];
                    float v2 = v * v;
                    s1 += v; s2 += v2; s3 += v2 * v; s4 += v2 * v2;
                }
            }
            #pragma unroll
            for (int m = 4; m <= 16; m <<= 1) {
                s1 += __shfl_xor_sync(0xffffffff, s1, m);
                s2 += __shfl_xor_sync(0xffffffff, s2, m);
                s3 += __shfl_xor_sync(0xffffffff, s3, m);
                s4 += __shfl_xor_sync(0xffffffff, s4, m);
            }
            if ((lane >> 2) == 0) {
                int idx = b * OUTC + om + osub + n8 * 8 + 2 * lane + hf;
                atomicAdd(&g_mom[idx],                 s1);
                atomicAdd(&g_mom[BB * OUTC + idx],     s2);
                atomicAdd(&g_mom[2 * BB * OUTC + idx], s3);
                atomicAdd(&g_mom[3 * BB * OUTC + idx], s4);
            }
        }
    }
}

// ---------------------------------------------------------------------------
// Kernel: finalize stats from raw moments
// ---------------------------------------------------------------------------
__global__ __launch_bounds__(256)
void stats_final_kernel()
{
    int idx = blockIdx.x * 256 + threadIdx.x;
    if (idx >= BB * OUTC) return;
    float r1 = g_mom[idx];
    float r2 = g_mom[BB * OUTC + idx];
    float r3 = g_mom[2 * BB * OUTC + idx];
    float r4 = g_mom[3 * BB * OUTC + idx];
    const float n = (float)TT;
    float m   = r1 / n;
    float ex2 = r2 / n, ex3 = r3 / n, ex4 = r4 / n;
    float var = (r2 - n * m * m) / (n - 1.0f);
    var = fmaxf(var, 0.f);
    float sd = sqrtf(var);
    float sc = fmaxf(sd, 0.01f);
    float m2 = m * m;
    float m3c = ex3 - 3.f * m * ex2 + 2.f * m * m2;
    float m4c = ex4 - 4.f * m * ex3 + 6.f * m2 * ex2 - 3.f * m2 * m2;
    int b = idx >> 9, o = idx & 511;
    float* st = g_stats + (long)b * (4 * OUTC);
    st[o]            = m;
    st[OUTC + o]     = sd;
    st[2 * OUTC + o] = m3c / (sc * sc * sc);
    st[3 * OUTC + o] = m4c / (sc * sc * sc * sc);
}

// ---------------------------------------------------------------------------
// Kernel: selection MLP + softmax -> g_s
// ---------------------------------------------------------------------------
__global__ __launch_bounds__(512)
void select_kernel(const float* __restrict__ sel_W1, const float* __restrict__ sel_b1,
                   const float* __restrict__ sel_W2, const float* __restrict__ sel_b2)
{
    const int b = blockIdx.x;
    const int tid = threadIdx.x;
    const int warp = tid >> 5, lane = tid & 31;

    __shared__ float sstats[4 * OUTC];
    __shared__ float sz[OUTC];
    __shared__ float ssv[NBR * OUTC];

    for (int i = tid; i < 4 * OUTC; i += 512)
        sstats[i] = g_stats[(long)b * (4 * OUTC) + i];
    __syncthreads();

    for (int r = warp; r < OUTC; r += 16) {
        float p = 0.f;
        for (int c = lane; c < 4 * OUTC; c += 32)
            p = fmaf(sel_W1[(long)r * (4 * OUTC) + c], sstats[c], p);
        p += __shfl_xor_sync(0xffffffff, p, 16);
        p += __shfl_xor_sync(0xffffffff, p, 8);
        p += __shfl_xor_sync(0xffffffff, p, 4);
        p += __shfl_xor_sync(0xffffffff, p, 2);
        p += __shfl_xor_sync(0xffffffff, p, 1);
        if (lane == 0) sz[r] = p + sel_b1[r];
    }
    __syncthreads();

    for (int idx = warp; idx < NBR * OUTC; idx += 16) {
        float p = 0.f;
        for (int c = lane; c < OUTC; c += 32)
            p = fmaf(sel_W2[(long)idx * OUTC + c], sz[c], p);
        p += __shfl_xor_sync(0xffffffff, p, 16);
        p += __shfl_xor_sync(0xffffffff, p, 8);
        p += __shfl_xor_sync(0xffffffff, p, 4);
        p += __shfl_xor_sync(0xffffffff, p, 2);
        p += __shfl_xor_sync(0xffffffff, p, 1);
        if (lane == 0) ssv[idx] = p + sel_b2[idx];
    }
    __syncthreads();

    if (tid < OUTC) {
        float v0 = ssv[tid], v1 = ssv[OUTC + tid], v2 = ssv[2 * OUTC + tid];
        float mx = fmaxf(v0, fmaxf(v1, v2));
        float e0 = __expf(v0 - mx), e1 = __expf(v1 - mx), e2 = __expf(v2 - mx);
        float inv = 1.f / (e0 + e1 + e2);
        float* sp = g_s + (long)b * (NBR * OUTC);
        sp[tid]            = e0 * inv;
        sp[OUTC + tid]     = e1 * inv;
        sp[2 * OUTC + tid] = e2 * inv;
    }
}

// ---------------------------------------------------------------------------
// Kernel: combine -- mirrors conv fragment layout.
// grid (21, 4, 16), 384 threads; out[b,o,t] = sum_i s[b,i,o]*f[i,b,o,t]
// ---------------------------------------------------------------------------
__global__ __launch_bounds__(384)
void combine_kernel(float* __restrict__ out)
{
    const int bx = blockIdx.x, by = blockIdx.y, b = blockIdx.z;
    const int t0 = bx * 96;
    const int om = by * 128;
    const int tid = threadIdx.x;
    const int warp = tid >> 5, lane = tid & 31;
    const int tsub = (warp >> 2) * 32;
    const int osub = (warp & 3) * 32;

    const long fbase = ((((long)b * 4 + by) * 21 + bx) * 12 + warp) * 512 + lane;
    const float* sp = g_s + (long)b * (NBR * OUTC);

    float sv[3][4][2];
    #pragma unroll
    for (int n8 = 0; n8 < 4; n8++) {
        int o = om + osub + n8 * 8 + 2 * (lane & 3);
        #pragma unroll
        for (int br = 0; br < 3; br++) {
            sv[br][n8][0] = sp[br * OUTC + o];
            sv[br][n8][1] = sp[br * OUTC + o + 1];
        }
    }

    #pragma unroll
    for (int mg = 0; mg < 2; mg++) {
        #pragma unroll
        for (int t8 = 0; t8 < 2; t8++) {
            int t = t0 + tsub + mg * 16 + (lane >> 2) + t8 * 8;
            if (t >= TT) continue;
            #pragma unroll
            for (int n8 = 0; n8 < 4; n8++) {
                long w = fbase + mg * 256 + t8 * 128 + n8 * 32;
                uint32_t u0 = g_fh[w];
                uint32_t u1 = g_fh[w + FBRW];
                uint32_t u2 = g_fh[w + 2 * FBRW];
                float2 f0 = __half22float2(*reinterpret_cast<__half2*>(&u0));
                float2 f1 = __half22float2(*reinterpret_cast<__half2*>(&u1));
                float2 f2 = __half22float2(*reinterpret_cast<__half2*>(&u2));
                float r0 = sv[0][n8][0] * f0.x + sv[1][n8][0] * f1.x + sv[2][n8][0] * f2.x;
                float r1 = sv[0][n8][1] * f0.y + sv[1][n8][1] * f1.y + sv[2][n8][1] * f2.y;
                int o = om + osub + n8 * 8 + 2 * (lane & 3);
                out[((long)b * OUTC + o) * TT + t]     = r0;
                out[((long)b * OUTC + o + 1) * TT + t] = r1;
            }
        }
    }
}

// ---------------------------------------------------------------------------
extern "C" void kernel_launch(void* const* d_in, const int* in_sizes, int n_in,
                              void* d_out, int out_size)
{
    const float* x         = (const float*)d_in[0];
    const float* bn1_gamma = (const float*)d_in[1];
    const float* bn1_beta  = (const float*)d_in[2];
    const float* bn1_mean  = (const float*)d_in[3];
    const float* bn1_var   = (const float*)d_in[4];
    const float* W1        = (const float*)d_in[5];
    const float* bn2_gamma = (const float*)d_in[6];
    const float* bn2_beta  = (const float*)d_in[7];
    const float* bn2_mean  = (const float*)d_in[8];
    const float* bn2_var   = (const float*)d_in[9];
    const float* conv_w    = (const float*)d_in[10];
    const float* sel_W1    = (const float*)d_in[11];
    const float* sel_b1    = (const float*)d_in[12];
    const float* sel_W2    = (const float*)d_in[13];
    const float* sel_b2    = (const float*)d_in[14];
    float* out = (float*)d_out;

    cudaFuncSetAttribute(conv_mma_kernel,
                         cudaFuncAttributeMaxDynamicSharedMemorySize, CSM_BYTES);

    prep_bn_kernel<<<1, 1024>>>(bn1_gamma, bn1_beta, bn1_mean, bn1_var,
                                bn2_gamma, bn2_beta, bn2_mean, bn2_var);
    prep_w1_kernel<<<(512 * 512 + 255) / 256, 256>>>(W1);
    prep_wc_kernel<<<(9 * 512 * 256 + 255) / 256, 256>>>(conv_w);
    {
        dim3 g(32, 16, BB);
        prep_x_kernel<<<g, 256>>>(x);
    }
    {
        dim3 g(16, 4, BB);
        gemm_mma_kernel<<<g, 256>>>();
    }
    {
        dim3 g(21, 4, BB);
        conv_mma_kernel<<<g, 384, CSM_BYTES>>>();
    }
    stats_final_kernel<<<(BB * OUTC + 255) / 256, 256>>>();
    select_kernel<<<BB, 512>>>(sel_W1, sel_b1, sel_W2, sel_b2);
    {
        dim3 g(21, 4, BB);
        combine_kernel<<<g, 384>>>(out);
    }
}

// round 16
// speedup vs baseline: 1.0019x; 1.0019x over previous
#include <cuda_runtime.h>
#include <cuda_fp16.h>
#include <stdint.h>

// Problem constants
#define BB   16
#define CIN  1024
#define TT   2000
#define BNC  512
#define OUTC 512
#define NBR  3
#define FSZ  (BB * OUTC * TT)

// Fragment-native branch-output layout:
//   word = [b][oy(4)][tx(21)][warp(12)][mg(2)][t8(2)][n8(4)][lane(32)]
#define FBRW 8257536L     // 16*4*21*12*512 words per branch

// ---------------------------------------------------------------------------
// Device scratch (fp16 pairs in uint32)
// ---------------------------------------------------------------------------
__device__ uint32_t g_xi[(long)BB * TT * 64 * 8];      // 65.5 MB
__device__ uint32_t g_h2i[(long)BB * TT * 32 * 8];     // 32.7 MB
__device__ uint32_t g_w1p[64 * 512 * 8];               // 1 MB
__device__ uint32_t g_wcp[9 * 32 * 512 * 8];           // 4.7 MB
__device__ uint32_t g_fh[3L * FBRW];                   // 99 MB fragment-native
__device__ float g_mom[4 * BB * OUTC];
__device__ float g_stats[BB * 4 * OUTC];
__device__ float g_s[BB * NBR * OUTC];
__device__ float g_a1[CIN], g_b1[CIN], g_a2[BNC], g_b2[BNC];

// ---------------------------------------------------------------------------
__device__ __forceinline__ uint32_t pack2h(__half a, __half b) {
    return (uint32_t)__half_as_ushort(a) | ((uint32_t)__half_as_ushort(b) << 16);
}
__device__ __forceinline__ void mma16816h(float* d, const uint32_t* a, const uint32_t* b) {
    asm volatile(
        "mma.sync.aligned.m16n8k16.row.col.f32.f16.f16.f32 "
        "{%0,%1,%2,%3}, {%4,%5,%6,%7}, {%8,%9}, {%0,%1,%2,%3};\n"
        : "+f"(d[0]), "+f"(d[1]), "+f"(d[2]), "+f"(d[3])
        : "r"(a[0]), "r"(a[1]), "r"(a[2]), "r"(a[3]), "r"(b[0]), "r"(b[1]));
}
__device__ __forceinline__ void ldsm4(uint32_t* r, uint32_t addr) {
    asm volatile("ldmatrix.sync.aligned.m8n8.x4.shared.b16 {%0,%1,%2,%3}, [%4];"
                 : "=r"(r[0]), "=r"(r[1]), "=r"(r[2]), "=r"(r[3]) : "r"(addr));
}
__device__ __forceinline__ uint32_t saddr(const void* p) {
    return (uint32_t)__cvta_generic_to_shared(p);
}
__device__ __forceinline__ void cpasync16(uint32_t dst, const void* src, int szbytes) {
    asm volatile("cp.async.cg.shared.global [%0], [%1], 16, %2;\n"
                 :: "r"(dst), "l"(src), "r"(szbytes));
}
#define CP_COMMIT() asm volatile("cp.async.commit_group;\n" ::: "memory")
#define CP_WAIT1()  asm volatile("cp.async.wait_group 1;\n" ::: "memory")
#define CP_WAIT0()  asm volatile("cp.async.wait_group 0;\n" ::: "memory")

// ---------------------------------------------------------------------------
// Kernel: fold BN params + zero moment accumulators
// ---------------------------------------------------------------------------
__global__ void prep_bn_kernel(const float* __restrict__ g1, const float* __restrict__ be1,
                               const float* __restrict__ m1, const float* __restrict__ v1,
                               const float* __restrict__ g2, const float* __restrict__ be2,
                               const float* __restrict__ m2, const float* __restrict__ v2)
{
    int i = threadIdx.x;
    if (i < CIN) {
        float inv = g1[i] * rsqrtf(v1[i] + 1e-5f);
        g_a1[i] = inv;
        g_b1[i] = be1[i] - m1[i] * inv;
    }
    if (i < BNC) {
        float inv = g2[i] * rsqrtf(v2[i] + 1e-5f);
        g_a2[i] = inv;
        g_b2[i] = be2[i] - m2[i] * inv;
    }
    for (int j = i; j < 4 * BB * OUTC; j += 1024) g_mom[j] = 0.f;
}

// ---------------------------------------------------------------------------
// Kernel: fp16 W1 -> g_w1p  [ch][o][8 words]
// ---------------------------------------------------------------------------
__global__ void prep_w1_kernel(const float* __restrict__ W1)
{
    int idx = blockIdx.x * 256 + threadIdx.x;
    if (idx >= 512 * 512) return;
    int o  = idx >> 9;
    int c2 = idx & 511;
    float w0 = W1[o * CIN + 2 * c2];
    float w1 = W1[o * CIN + 2 * c2 + 1];
    g_w1p[((long)(c2 >> 3) * 512 + o) * 8 + (c2 & 7)] =
        pack2h(__float2half_rn(w0), __float2half_rn(w1));
}

// ---------------------------------------------------------------------------
// Kernel: fp16 conv_w -> g_wcp  [comb][ch][o][8 words].  conv_w: [i][o][c][k]
// ---------------------------------------------------------------------------
__global__ void prep_wc_kernel(const float* __restrict__ conv_w)
{
    int idx = blockIdx.x * 256 + threadIdx.x;
    if (idx >= 9 * 512 * 256) return;
    int comb = idx / (512 * 256);
    int r = idx - comb * (512 * 256);
    int o  = r >> 8;
    int c2 = r & 255;
    int i = comb / 3, k = comb % 3;
    int c = 2 * c2;
    float w0 = conv_w[(((long)i * 512 + o) * 512 + c) * 3 + k];
    float w1 = conv_w[(((long)i * 512 + o) * 512 + c + 1) * 3 + k];
    g_wcp[(((long)comb * 32 + (c2 >> 3)) * 512 + o) * 8 + (c2 & 7)] =
        pack2h(__float2half_rn(w0), __float2half_rn(w1));
}

// ---------------------------------------------------------------------------
// Kernel: prep_x -- bn1+relu, round to fp16, into g_xi (smem transpose)
// ---------------------------------------------------------------------------
__global__ __launch_bounds__(256)
void prep_x_kernel(const float* __restrict__ x)
{
    __shared__ float sm[32 * 132];
    const int c0 = blockIdx.x * 32;
    const int t0 = blockIdx.y * 128;
    const int b  = blockIdx.z;
    const int tid = threadIdx.x;

    for (int i = tid; i < 1024; i += 256) {
        int c = i >> 5, t4 = i & 31;
        int t = t0 + t4 * 4;
        float4 v = make_float4(0.f, 0.f, 0.f, 0.f);
        if (t < TT) v = *reinterpret_cast<const float4*>(&x[((long)(b * CIN + c0 + c)) * TT + t]);
        *reinterpret_cast<float4*>(&sm[c * 132 + t4 * 4]) = v;
    }
    __syncthreads();

    for (int i = tid; i < 512; i += 256) {
        int t   = i >> 2;
        int ch2 = (i >> 1) & 1;
        int q   = i & 1;
        if (t0 + t >= TT) continue;
        uint32_t w[4];
        #pragma unroll
        for (int j = 0; j < 4; j++) {
            int c = ch2 * 16 + q * 8 + 2 * j;
            int cg = c0 + c;
            float v0 = fmaxf(fmaf(sm[c * 132 + t],       g_a1[cg],     g_b1[cg]),     0.f);
            float v1 = fmaxf(fmaf(sm[(c + 1) * 132 + t], g_a1[cg + 1], g_b1[cg + 1]), 0.f);
            w[j] = pack2h(__float2half_rn(v0), __float2half_rn(v1));
        }
        long widx = (((long)b * TT + t0 + t) * 64 + (c0 >> 4) + ch2) * 8 + q * 4;
        *reinterpret_cast<uint4*>(&g_xi[widx]) = make_uint4(w[0], w[1], w[2], w[3]);
    }
}

// ---------------------------------------------------------------------------
// GEMM: h2 = relu(bn2(W1 @ xbn)).  Pure fp16 MMA, 2-stage cp.async.
// Block 128t x 128o, 256 threads (8 warps: 4t x 2o), warp 32t x 64o.
// ---------------------------------------------------------------------------
__global__ __launch_bounds__(256, 2)
void gemm_mma_kernel()
{
    __shared__ uint32_t As[2][128 * 12];
    __shared__ uint32_t Bs[2][128 * 12];
    __shared__ float bn2s[256];

    const int t0 = blockIdx.x * 128;
    const int om = blockIdx.y * 128;
    const int b  = blockIdx.z;

    const int tid  = threadIdx.x;
    const int warp = tid >> 5, lane = tid & 31;
    const int wt = warp >> 1, wo = warp & 1;

    if (tid < 128) {
        bn2s[tid]       = g_a2[om + tid];
        bn2s[128 + tid] = g_b2[om + tid];
    }

    float acc[2][8][4];
    #pragma unroll
    for (int m = 0; m < 2; m++)
        #pragma unroll
        for (int n = 0; n < 8; n++)
            #pragma unroll
            for (int j = 0; j < 4; j++) acc[m][n][j] = 0.f;

    const uint32_t as_base = saddr(As), bs_base = saddr(Bs);
    const int lrA = lane & 15, lwA = ((lane >> 4) & 1) * 4;
    uint32_t aA[2];
    #pragma unroll
    for (int mt = 0; mt < 2; mt++) {
        uint32_t r = (uint32_t)(wt * 32 + mt * 16 + lrA);
        aA[mt] = as_base + (r * 12 + lwA) * 4;
    }
    const int rB = ((lane >> 4) & 1) * 8 + (lane & 7);
    const int wB = ((lane >> 3) & 1) * 4;
    uint32_t aB[4];
    #pragma unroll
    for (int g = 0; g < 4; g++) {
        uint32_t r = (uint32_t)(wo * 64 + g * 16 + rB);
        aB[g] = bs_base + (r * 12 + wB) * 4;
    }

    auto fill = [&](int st, int ch) {
        {
            int r = tid >> 1, q = tid & 1;
            int t = t0 + r;
            int ok = (t < TT);
            const void* gp = &g_xi[(((long)b * TT + (ok ? t : 0)) * 64 + ch) * 8 + q * 4];
            cpasync16(as_base + (uint32_t)st * 6144 + (r * 12 + q * 4) * 4, gp, ok ? 16 : 0);
        }
        {
            int r = tid >> 1, q = tid & 1;
            const void* gp = &g_w1p[((long)ch * 512 + om + r) * 8 + q * 4];
            cpasync16(bs_base + (uint32_t)st * 6144 + (r * 12 + q * 4) * 4, gp, 16);
        }
    };

    fill(0, 0);
    CP_COMMIT();

    for (int ch = 0; ch < 64; ch++) {
        int st = ch & 1;
        if (ch + 1 < 64) {
            fill(st ^ 1, ch + 1);
            CP_COMMIT();
            CP_WAIT1();
        } else {
            CP_WAIT0();
        }
        __syncthreads();

        uint32_t soff = (uint32_t)st * 6144;
        uint32_t ah[2][4];
        ldsm4(ah[0], aA[0] + soff);
        ldsm4(ah[1], aA[1] + soff);

        #pragma unroll
        for (int g = 0; g < 4; g++) {
            uint32_t bh[4];
            ldsm4(bh, aB[g] + soff);
            #pragma unroll
            for (int mt = 0; mt < 2; mt++) {
                mma16816h(acc[mt][2 * g],     ah[mt], &bh[0]);
                mma16816h(acc[mt][2 * g + 1], ah[mt], &bh[2]);
            }
        }
        __syncthreads();
    }

    // epilogue: bn2+relu, round to fp16, store g_h2i
    #pragma unroll
    for (int mt = 0; mt < 2; mt++) {
        #pragma unroll
        for (int hf = 0; hf < 2; hf++) {
            int t = t0 + wt * 32 + mt * 16 + (lane >> 2) + hf * 8;
            if (t >= TT) continue;
            long tb = ((long)b * TT + t) * 256;
            #pragma unroll
            for (int n8 = 0; n8 < 8; n8++) {
                int ol = wo * 64 + n8 * 8 + 2 * (lane & 3);
                float v0 = fmaxf(fmaf(acc[mt][n8][hf * 2],     bn2s[ol],     bn2s[128 + ol]), 0.f);
                float v1 = fmaxf(fmaf(acc[mt][n8][hf * 2 + 1], bn2s[ol + 1], bn2s[129 + ol]), 0.f);
                int o = om + ol;
                g_h2i[tb + (long)(o >> 4) * 8 + ((o & 15) >> 1)] =
                    pack2h(__float2half_rn(v0), __float2half_rn(v1));
            }
        }
    }
}

// ---------------------------------------------------------------------------
// Conv: 3-branch dilated conv, pure fp16 MMA, 2-stage cp.async.
// Block 96t x 128o, 384 threads (12 warps: 3t x 4o), warp 32t x 32o.
// Epilogue A: direct register stores to fragment-native g_fh.
// Epilogue B: branch-sum raw moments (shfl + atomics), OOB-t predicated.
// ---------------------------------------------------------------------------
#define CSTG_WORDS 15048
#define CSM_BYTES  (2 * CSTG_WORDS * 4)

__global__ __launch_bounds__(384, 1)
void conv_mma_kernel()
{
    extern __shared__ uint32_t cs[];

    const int t0 = blockIdx.x * 96;
    const int om = blockIdx.y * 128;
    const int b  = blockIdx.z;

    const int tid  = threadIdx.x;
    const int warp = tid >> 5, lane = tid & 31;
    const int tsub = (warp >> 2) * 32;   // 0,32,64
    const int osub = (warp & 3) * 32;    // 0,32,64,96

    float acc[3][2][4][4];   // [br][mg][n8][j]
    #pragma unroll
    for (int i = 0; i < 3; i++)
        #pragma unroll
        for (int m = 0; m < 2; m++)
            #pragma unroll
            for (int n = 0; n < 4; n++)
                #pragma unroll
                for (int j = 0; j < 4; j++) acc[i][m][n][j] = 0.f;

    const uint32_t cs_base  = saddr(cs);
    const uint32_t ws_base  = cs_base;
    const uint32_t hsp_base = cs_base + 13824 * 4;
    const int lrA = lane & 15, lwA = ((lane >> 4) & 1) * 4;
    const uint32_t aAbase = hsp_base + ((uint32_t)(tsub + lrA) * 12 + lwA) * 4;
    const int rB = ((lane >> 4) & 1) * 8 + (lane & 7);
    const int wB = ((lane >> 3) & 1) * 4;
    const uint32_t aB0 = ws_base + ((uint32_t)(osub + rB) * 12 + wB) * 4;

    auto fill = [&](int st, int ch) {
        uint32_t sb = (uint32_t)st * (CSTG_WORDS * 4);
        for (int i = tid; i < 2304; i += 384) {
            int comb = i >> 8;
            int r = i & 255;
            int o = r >> 1, q = r & 1;
            const void* gp = &g_wcp[(((long)comb * 32 + ch) * 512 + om + o) * 8 + q * 4];
            cpasync16(ws_base + sb + (uint32_t)(comb * 1536 + o * 12 + q * 4) * 4, gp, 16);
        }
        if (tid < 204) {
            int r = tid >> 1, q = tid & 1;
            int t = t0 - 3 + r;
            int ok = (t >= 0 && t < TT);
            const void* gp = &g_h2i[(((long)b * TT + (ok ? t : 0)) * 32 + ch) * 8 + q * 4];
            cpasync16(hsp_base + sb + (uint32_t)(r * 12 + q * 4) * 4, gp, ok ? 16 : 0);
        }
    };

    auto domma = [&](uint32_t soff, int comb, int br, uint32_t ah[2][4]) {
        #pragma unroll
        for (int g = 0; g < 2; g++) {
            uint32_t bh[4];
            ldsm4(bh, aB0 + soff + (uint32_t)(comb * 6144 + g * 768));
            #pragma unroll
            for (int mg = 0; mg < 2; mg++) {
                mma16816h(acc[br][mg][2 * g],     ah[mg], &bh[0]);
                mma16816h(acc[br][mg][2 * g + 1], ah[mg], &bh[2]);
            }
        }
    };

    fill(0, 0);
    CP_COMMIT();

    for (int ch = 0; ch < 32; ch++) {
        int st = ch & 1;
        if (ch + 1 < 32) {
            fill(st ^ 1, ch + 1);
            CP_COMMIT();
            CP_WAIT1();
        } else {
            CP_WAIT0();
        }
        __syncthreads();

        uint32_t soff = (uint32_t)st * (CSTG_WORDS * 4);
        uint32_t ah[2][4];

        // center taps (doff=3): combs 1,4,7 share A fragments
        {
            #pragma unroll
            for (int mg = 0; mg < 2; mg++)
                ldsm4(ah[mg], aAbase + soff + (uint32_t)(mg * 16 + 3) * 48);
            domma(soff, 1, 0, ah);
            domma(soff, 4, 1, ah);
            domma(soff, 7, 2, ah);
        }
        // off-center taps
        {
            const int combs[6] = {0, 2, 3, 5, 6, 8};
            const int doffs[6] = {2, 4, 1, 5, 0, 6};
            #pragma unroll
            for (int j = 0; j < 6; j++) {
                #pragma unroll
                for (int mg = 0; mg < 2; mg++)
                    ldsm4(ah[mg], aAbase + soff + (uint32_t)(mg * 16 + doffs[j]) * 48);
                domma(soff, combs[j], combs[j] / 3, ah);
            }
        }
        __syncthreads();
    }

    // --- epilogue A: direct fragment-native stores (coalesced, no smem) ---
    const long fbase = ((((long)b * 4 + blockIdx.y) * 21 + blockIdx.x) * 12 + warp) * 512 + lane;
    #pragma unroll
    for (int br = 0; br < 3; br++) {
        long bb2 = fbase + (long)br * FBRW;
        #pragma unroll
        for (int mg = 0; mg < 2; mg++) {
            #pragma unroll
            for (int n8 = 0; n8 < 4; n8++) {
                g_fh[bb2 + mg * 256 + n8 * 32] =
                    pack2h(__float2half_rn(acc[br][mg][n8][0]),
                           __float2half_rn(acc[br][mg][n8][1]));
                g_fh[bb2 + mg * 256 + 128 + n8 * 32] =
                    pack2h(__float2half_rn(acc[br][mg][n8][2]),
                           __float2half_rn(acc[br][mg][n8][3]));
            }
        }
    }

    // --- epilogue B: branch-sum raw moments, OOB-t predicated ---
    float tw[2][2];
    #pragma unroll
    for (int mg = 0; mg < 2; mg++)
        #pragma unroll
        for (int tt = 0; tt < 2; tt++)
            tw[mg][tt] = (t0 + tsub + mg * 16 + (lane >> 2) + tt * 8 < TT) ? 1.f : 0.f;

    #pragma unroll
    for (int n8 = 0; n8 < 4; n8++) {
        #pragma unroll
        for (int hf = 0; hf < 2; hf++) {
            float s1 = 0.f, s2 = 0.f, s3 = 0.f, s4 = 0.f;
            #pragma unroll
            for (int mg = 0; mg < 2; mg++) {
                #pragma unroll
                for (int tt = 0; tt < 2; tt++) {
                    float v = (acc[0][mg][n8][hf + 2 * tt] +
                               acc[1][mg][n8][hf + 2 * tt] +
                               acc[2][mg][n8][hf + 2 * tt]) * tw[mg][tt];
                    float v2 = v * v;
                    s1 += v; s2 += v2; s3 += v2 * v; s4 += v2 * v2;
                }
            }
            #pragma unroll
            for (int m = 4; m <= 16; m <<= 1) {
                s1 += __shfl_xor_sync(0xffffffff, s1, m);
                s2 += __shfl_xor_sync(0xffffffff, s2, m);
                s3 += __shfl_xor_sync(0xffffffff, s3, m);
                s4 += __shfl_xor_sync(0xffffffff, s4, m);
            }
            if ((lane >> 2) == 0) {
                int idx = b * OUTC + om + osub + n8 * 8 + 2 * lane + hf;
                atomicAdd(&g_mom[idx],                 s1);
                atomicAdd(&g_mom[BB * OUTC + idx],     s2);
                atomicAdd(&g_mom[2 * BB * OUTC + idx], s3);
                atomicAdd(&g_mom[3 * BB * OUTC + idx], s4);
            }
        }
    }
}

// ---------------------------------------------------------------------------
// Kernel: finalize stats from raw moments
// ---------------------------------------------------------------------------
__global__ __launch_bounds__(256)
void stats_final_kernel()
{
    int idx = blockIdx.x * 256 + threadIdx.x;
    if (idx >= BB * OUTC) return;
    float r1 = g_mom[idx];
    float r2 = g_mom[BB * OUTC + idx];
    float r3 = g_mom[2 * BB * OUTC + idx];
    float r4 = g_mom[3 * BB * OUTC + idx];
    const float n = (float)TT;
    float m   = r1 / n;
    float ex2 = r2 / n, ex3 = r3 / n, ex4 = r4 / n;
    float var = (r2 - n * m * m) / (n - 1.0f);
    var = fmaxf(var, 0.f);
    float sd = sqrtf(var);
    float sc = fmaxf(sd, 0.01f);
    float m2 = m * m;
    float m3c = ex3 - 3.f * m * ex2 + 2.f * m * m2;
    float m4c = ex4 - 4.f * m * ex3 + 6.f * m2 * ex2 - 3.f * m2 * m2;
    int b = idx >> 9, o = idx & 511;
    float* st = g_stats + (long)b * (4 * OUTC);
    st[o]            = m;
    st[OUTC + o]     = sd;
    st[2 * OUTC + o] = m3c / (sc * sc * sc);
    st[3 * OUTC + o] = m4c / (sc * sc * sc * sc);
}

// ---------------------------------------------------------------------------
// Kernel: selection MLP + softmax -> g_s
// ---------------------------------------------------------------------------
__global__ __launch_bounds__(512)
void select_kernel(const float* __restrict__ sel_W1, const float* __restrict__ sel_b1,
                   const float* __restrict__ sel_W2, const float* __restrict__ sel_b2)
{
    const int b = blockIdx.x;
    const int tid = threadIdx.x;
    const int warp = tid >> 5, lane = tid & 31;

    __shared__ float sstats[4 * OUTC];
    __shared__ float sz[OUTC];
    __shared__ float ssv[NBR * OUTC];

    for (int i = tid; i < 4 * OUTC; i += 512)
        sstats[i] = g_stats[(long)b * (4 * OUTC) + i];
    __syncthreads();

    for (int r = warp; r < OUTC; r += 16) {
        float p = 0.f;
        for (int c = lane; c < 4 * OUTC; c += 32)
            p = fmaf(sel_W1[(long)r * (4 * OUTC) + c], sstats[c], p);
        p += __shfl_xor_sync(0xffffffff, p, 16);
        p += __shfl_xor_sync(0xffffffff, p, 8);
        p += __shfl_xor_sync(0xffffffff, p, 4);
        p += __shfl_xor_sync(0xffffffff, p, 2);
        p += __shfl_xor_sync(0xffffffff, p, 1);
        if (lane == 0) sz[r] = p + sel_b1[r];
    }
    __syncthreads();

    for (int idx = warp; idx < NBR * OUTC; idx += 16) {
        float p = 0.f;
        for (int c = lane; c < OUTC; c += 32)
            p = fmaf(sel_W2[(long)idx * OUTC + c], sz[c], p);
        p += __shfl_xor_sync(0xffffffff, p, 16);
        p += __shfl_xor_sync(0xffffffff, p, 8);
        p += __shfl_xor_sync(0xffffffff, p, 4);
        p += __shfl_xor_sync(0xffffffff, p, 2);
        p += __shfl_xor_sync(0xffffffff, p, 1);
        if (lane == 0) ssv[idx] = p + sel_b2[idx];
    }
    __syncthreads();

    if (tid < OUTC) {
        float v0 = ssv[tid], v1 = ssv[OUTC + tid], v2 = ssv[2 * OUTC + tid];
        float mx = fmaxf(v0, fmaxf(v1, v2));
        float e0 = __expf(v0 - mx), e1 = __expf(v1 - mx), e2 = __expf(v2 - mx);
        float inv = 1.f / (e0 + e1 + e2);
        float* sp = g_s + (long)b * (NBR * OUTC);
        sp[tid]            = e0 * inv;
        sp[OUTC + tid]     = e1 * inv;
        sp[2 * OUTC + tid] = e2 * inv;
    }
}

// ---------------------------------------------------------------------------
// Kernel: combine -- fragment-native reads, smem transpose, float4 stores.
// grid (21, 4, 16), 384 threads.  Dynamic smem: 128*100 floats = 51.2 KB.
// ---------------------------------------------------------------------------
__global__ __launch_bounds__(384)
void combine_kernel(float* __restrict__ out)
{
    extern __shared__ float so[];   // so[o][t], row stride 100

    const int bx = blockIdx.x, by = blockIdx.y, b = blockIdx.z;
    const int t0 = bx * 96;
    const int om = by * 128;
    const int tid = threadIdx.x;
    const int warp = tid >> 5, lane = tid & 31;
    const int tsub = (warp >> 2) * 32;
    const int osub = (warp & 3) * 32;

    const long fbase = ((((long)b * 4 + by) * 21 + bx) * 12 + warp) * 512 + lane;
    const float* sp = g_s + (long)b * (NBR * OUTC);

    float sv[3][4][2];
    #pragma unroll
    for (int n8 = 0; n8 < 4; n8++) {
        int o = om + osub + n8 * 8 + 2 * (lane & 3);
        #pragma unroll
        for (int br = 0; br < 3; br++) {
            sv[br][n8][0] = sp[br * OUTC + o];
            sv[br][n8][1] = sp[br * OUTC + o + 1];
        }
    }

    #pragma unroll
    for (int mg = 0; mg < 2; mg++) {
        #pragma unroll
        for (int t8 = 0; t8 < 2; t8++) {
            int tl = tsub + mg * 16 + (lane >> 2) + t8 * 8;
            #pragma unroll
            for (int n8 = 0; n8 < 4; n8++) {
                long w = fbase + mg * 256 + t8 * 128 + n8 * 32;
                uint32_t u0 = g_fh[w];
                uint32_t u1 = g_fh[w + FBRW];
                uint32_t u2 = g_fh[w + 2 * FBRW];
                float2 f0 = __half22float2(*reinterpret_cast<__half2*>(&u0));
                float2 f1 = __half22float2(*reinterpret_cast<__half2*>(&u1));
                float2 f2 = __half22float2(*reinterpret_cast<__half2*>(&u2));
                float r0 = sv[0][n8][0] * f0.x + sv[1][n8][0] * f1.x + sv[2][n8][0] * f2.x;
                float r1 = sv[0][n8][1] * f0.y + sv[1][n8][1] * f1.y + sv[2][n8][1] * f2.y;
                int ol = osub + n8 * 8 + 2 * (lane & 3);
                so[ol * 100 + tl]       = r0;
                so[(ol + 1) * 100 + tl] = r1;
            }
        }
    }
    __syncthreads();

    for (int i = tid; i < 3072; i += 384) {
        int o  = i / 24;
        int t4 = i - o * 24;
        int t = t0 + t4 * 4;
        if (t < TT) {
            float4 v = *reinterpret_cast<const float4*>(&so[o * 100 + t4 * 4]);
            *reinterpret_cast<float4*>(&out[((long)b * OUTC + om + o) * TT + t]) = v;
        }
    }
}

// ---------------------------------------------------------------------------
extern "C" void kernel_launch(void* const* d_in, const int* in_sizes, int n_in,
                              void* d_out, int out_size)
{
    const float* x         = (const float*)d_in[0];
    const float* bn1_gamma = (const float*)d_in[1];
    const float* bn1_beta  = (const float*)d_in[2];
    const float* bn1_mean  = (const float*)d_in[3];
    const float* bn1_var   = (const float*)d_in[4];
    const float* W1        = (const float*)d_in[5];
    const float* bn2_gamma = (const float*)d_in[6];
    const float* bn2_beta  = (const float*)d_in[7];
    const float* bn2_mean  = (const float*)d_in[8];
    const float* bn2_var   = (const float*)d_in[9];
    const float* conv_w    = (const float*)d_in[10];
    const float* sel_W1    = (const float*)d_in[11];
    const float* sel_b1    = (const float*)d_in[12];
    const float* sel_W2    = (const float*)d_in[13];
    const float* sel_b2    = (const float*)d_in[14];
    float* out = (float*)d_out;

    cudaFuncSetAttribute(conv_mma_kernel,
                         cudaFuncAttributeMaxDynamicSharedMemorySize, CSM_BYTES);
    cudaFuncSetAttribute(combine_kernel,
                         cudaFuncAttributeMaxDynamicSharedMemorySize, 128 * 100 * 4);

    prep_bn_kernel<<<1, 1024>>>(bn1_gamma, bn1_beta, bn1_mean, bn1_var,
                                bn2_gamma, bn2_beta, bn2_mean, bn2_var);
    prep_w1_kernel<<<(512 * 512 + 255) / 256, 256>>>(W1);
    prep_wc_kernel<<<(9 * 512 * 256 + 255) / 256, 256>>>(conv_w);
    {
        dim3 g(32, 16, BB);
        prep_x_kernel<<<g, 256>>>(x);
    }
    {
        dim3 g(16, 4, BB);
        gemm_mma_kernel<<<g, 256>>>();
    }
    {
        dim3 g(21, 4, BB);
        conv_mma_kernel<<<g, 384, CSM_BYTES>>>();
    }
    stats_final_kernel<<<(BB * OUTC + 255) / 256, 256>>>();
    select_kernel<<<BB, 512>>>(sel_W1, sel_b1, sel_W2, sel_b2);
    {
        dim3 g(21, 4, BB);
        combine_kernel<<<g, 384, 128 * 100 * 4>>>(out);
    }
}

// round 17
// speedup vs baseline: 1.0277x; 1.0258x over previous
#include <cuda_runtime.h>
#include <cuda_fp16.h>
#include <stdint.h>

// Problem constants
#define BB   16
#define CIN  1024
#define TT   2000
#define BNC  512
#define OUTC 512
#define NBR  3
#define FSZ  (BB * OUTC * TT)

// ---------------------------------------------------------------------------
// Device scratch (fp16 pairs in uint32)
//   g_xi : [b][t][ch(64)][c2l(8)]       single-fp16 bn1-relu'd x
//   g_h2i: [b][t][ch(32)][c2l(8)]       single-fp16 h2
//   g_w1p: [ch(64)][o(512)][c2l(8)]     single-fp16 W1
//   g_wcp: [comb(9)][ch(32)][o(512)][c2l(8)] single-fp16 conv weights
//   g_fh : fp16 branch outputs [br][b][o][t] (pairs in uint32)
// ---------------------------------------------------------------------------
__device__ uint32_t g_xi[(long)BB * TT * 64 * 8];      // 65.5 MB
__device__ uint32_t g_h2i[(long)BB * TT * 32 * 8];     // 32.7 MB
__device__ uint32_t g_w1p[64 * 512 * 8];               // 1 MB
__device__ uint32_t g_wcp[9 * 32 * 512 * 8];           // 4.7 MB
__device__ uint32_t g_fh[3L * FSZ / 2];                // 98.3 MB
__device__ float g_mom[4 * BB * OUTC];                 // raw moment sums
__device__ float g_stats[BB * 4 * OUTC];
__device__ float g_s[BB * NBR * OUTC];
__device__ float g_a1[CIN], g_b1[CIN], g_a2[BNC], g_b2[BNC];

// ---------------------------------------------------------------------------
__device__ __forceinline__ uint32_t pack2h(__half a, __half b) {
    return (uint32_t)__half_as_ushort(a) | ((uint32_t)__half_as_ushort(b) << 16);
}
__device__ __forceinline__ void mma16816h(float* d, const uint32_t* a, const uint32_t* b) {
    asm volatile(
        "mma.sync.aligned.m16n8k16.row.col.f32.f16.f16.f32 "
        "{%0,%1,%2,%3}, {%4,%5,%6,%7}, {%8,%9}, {%0,%1,%2,%3};\n"
        : "+f"(d[0]), "+f"(d[1]), "+f"(d[2]), "+f"(d[3])
        : "r"(a[0]), "r"(a[1]), "r"(a[2]), "r"(a[3]), "r"(b[0]), "r"(b[1]));
}
__device__ __forceinline__ void ldsm4(uint32_t* r, uint32_t addr) {
    asm volatile("ldmatrix.sync.aligned.m8n8.x4.shared.b16 {%0,%1,%2,%3}, [%4];"
                 : "=r"(r[0]), "=r"(r[1]), "=r"(r[2]), "=r"(r[3]) : "r"(addr));
}
__device__ __forceinline__ uint32_t saddr(const void* p) {
    return (uint32_t)__cvta_generic_to_shared(p);
}
__device__ __forceinline__ void cpasync16(uint32_t dst, const void* src, int szbytes) {
    asm volatile("cp.async.cg.shared.global [%0], [%1], 16, %2;\n"
                 :: "r"(dst), "l"(src), "r"(szbytes));
}
#define CP_COMMIT() asm volatile("cp.async.commit_group;\n" ::: "memory")
#define CP_WAIT1()  asm volatile("cp.async.wait_group 1;\n" ::: "memory")
#define CP_WAIT0()  asm volatile("cp.async.wait_group 0;\n" ::: "memory")

// ---------------------------------------------------------------------------
// Kernel: fold BN params + zero moment accumulators
// ---------------------------------------------------------------------------
__global__ void prep_bn_kernel(const float* __restrict__ g1, const float* __restrict__ be1,
                               const float* __restrict__ m1, const float* __restrict__ v1,
                               const float* __restrict__ g2, const float* __restrict__ be2,
                               const float* __restrict__ m2, const float* __restrict__ v2)
{
    int i = threadIdx.x;
    if (i < CIN) {
        float inv = g1[i] * rsqrtf(v1[i] + 1e-5f);
        g_a1[i] = inv;
        g_b1[i] = be1[i] - m1[i] * inv;
    }
    if (i < BNC) {
        float inv = g2[i] * rsqrtf(v2[i] + 1e-5f);
        g_a2[i] = inv;
        g_b2[i] = be2[i] - m2[i] * inv;
    }
    for (int j = i; j < 4 * BB * OUTC; j += 1024) g_mom[j] = 0.f;
}

// ---------------------------------------------------------------------------
// Kernel: fp16 W1 -> g_w1p  [ch][o][8 words]
// ---------------------------------------------------------------------------
__global__ void prep_w1_kernel(const float* __restrict__ W1)
{
    int idx = blockIdx.x * 256 + threadIdx.x;
    if (idx >= 512 * 512) return;
    int o  = idx >> 9;
    int c2 = idx & 511;
    float w0 = W1[o * CIN + 2 * c2];
    float w1 = W1[o * CIN + 2 * c2 + 1];
    g_w1p[((long)(c2 >> 3) * 512 + o) * 8 + (c2 & 7)] =
        pack2h(__float2half_rn(w0), __float2half_rn(w1));
}

// ---------------------------------------------------------------------------
// Kernel: fp16 conv_w -> g_wcp  [comb][ch][o][8 words].  conv_w: [i][o][c][k]
// ---------------------------------------------------------------------------
__global__ void prep_wc_kernel(const float* __restrict__ conv_w)
{
    int idx = blockIdx.x * 256 + threadIdx.x;
    if (idx >= 9 * 512 * 256) return;
    int comb = idx / (512 * 256);
    int r = idx - comb * (512 * 256);
    int o  = r >> 8;
    int c2 = r & 255;
    int i = comb / 3, k = comb % 3;
    int c = 2 * c2;
    float w0 = conv_w[(((long)i * 512 + o) * 512 + c) * 3 + k];
    float w1 = conv_w[(((long)i * 512 + o) * 512 + c + 1) * 3 + k];
    g_wcp[(((long)comb * 32 + (c2 >> 3)) * 512 + o) * 8 + (c2 & 7)] =
        pack2h(__float2half_rn(w0), __float2half_rn(w1));
}

// ---------------------------------------------------------------------------
// Kernel: prep_x -- bn1+relu, round to fp16, into g_xi (smem transpose)
// ---------------------------------------------------------------------------
__global__ __launch_bounds__(256)
void prep_x_kernel(const float* __restrict__ x)
{
    __shared__ float sm[32 * 132];
    const int c0 = blockIdx.x * 32;
    const int t0 = blockIdx.y * 128;
    const int b  = blockIdx.z;
    const int tid = threadIdx.x;

    for (int i = tid; i < 1024; i += 256) {
        int c = i >> 5, t4 = i & 31;
        int t = t0 + t4 * 4;
        float4 v = make_float4(0.f, 0.f, 0.f, 0.f);
        if (t < TT) v = *reinterpret_cast<const float4*>(&x[((long)(b * CIN + c0 + c)) * TT + t]);
        *reinterpret_cast<float4*>(&sm[c * 132 + t4 * 4]) = v;
    }
    __syncthreads();

    for (int i = tid; i < 512; i += 256) {
        int t   = i >> 2;
        int ch2 = (i >> 1) & 1;
        int q   = i & 1;
        if (t0 + t >= TT) continue;
        uint32_t w[4];
        #pragma unroll
        for (int j = 0; j < 4; j++) {
            int c = ch2 * 16 + q * 8 + 2 * j;
            int cg = c0 + c;
            float v0 = fmaxf(fmaf(sm[c * 132 + t],       g_a1[cg],     g_b1[cg]),     0.f);
            float v1 = fmaxf(fmaf(sm[(c + 1) * 132 + t], g_a1[cg + 1], g_b1[cg + 1]), 0.f);
            w[j] = pack2h(__float2half_rn(v0), __float2half_rn(v1));
        }
        long widx = (((long)b * TT + t0 + t) * 64 + (c0 >> 4) + ch2) * 8 + q * 4;
        *reinterpret_cast<uint4*>(&g_xi[widx]) = make_uint4(w[0], w[1], w[2], w[3]);
    }
}

// ---------------------------------------------------------------------------
// GEMM: h2 = relu(bn2(W1 @ xbn)).  Pure fp16 MMA, 2-stage cp.async,
// K-chunk 32 (two k16 halves per iteration; 32 iterations, half the barriers).
// Block 128t x 128o, 256 threads (8 warps: 4t x 2o), warp 32t x 64o.
// Stage: rows of 16 words padded to 20; 128*20=2560 words per matrix.
// ---------------------------------------------------------------------------
__global__ __launch_bounds__(256, 2)
void gemm_mma_kernel()
{
    __shared__ uint32_t As[2][128 * 20];
    __shared__ uint32_t Bs[2][128 * 20];
    __shared__ float bn2s[256];

    const int t0 = blockIdx.x * 128;
    const int om = blockIdx.y * 128;
    const int b  = blockIdx.z;

    const int tid  = threadIdx.x;
    const int warp = tid >> 5, lane = tid & 31;
    const int wt = warp >> 1, wo = warp & 1;

    if (tid < 128) {
        bn2s[tid]       = g_a2[om + tid];
        bn2s[128 + tid] = g_b2[om + tid];
    }

    float acc[2][8][4];
    #pragma unroll
    for (int m = 0; m < 2; m++)
        #pragma unroll
        for (int n = 0; n < 8; n++)
            #pragma unroll
            for (int j = 0; j < 4; j++) acc[m][n][j] = 0.f;

    const uint32_t as_base = saddr(As), bs_base = saddr(Bs);
    const int lrA = lane & 15, lwA = ((lane >> 4) & 1) * 4;
    uint32_t aA[2];
    #pragma unroll
    for (int mt = 0; mt < 2; mt++) {
        uint32_t r = (uint32_t)(wt * 32 + mt * 16 + lrA);
        aA[mt] = as_base + (r * 20 + lwA) * 4;
    }
    const int rB = ((lane >> 4) & 1) * 8 + (lane & 7);
    const int wB = ((lane >> 3) & 1) * 4;
    uint32_t aB[4];
    #pragma unroll
    for (int g = 0; g < 4; g++) {
        uint32_t r = (uint32_t)(wo * 64 + g * 16 + rB);
        aB[g] = bs_base + (r * 20 + wB) * 4;
    }

    // fill chunk C (covers ch = 2C, 2C+1): 512 uint4 per matrix
    auto fill = [&](int st, int C) {
        #pragma unroll
        for (int rep = 0; rep < 2; rep++) {
            int i = tid + rep * 256;
            int r = i >> 2, q = i & 3;          // q: 0,1 -> ch 2C; 2,3 -> ch 2C+1
            int t = t0 + r;
            int ok = (t < TT);
            const void* gp = &g_xi[(((long)b * TT + (ok ? t : 0)) * 64 + 2 * C + (q >> 1)) * 8 + (q & 1) * 4];
            cpasync16(as_base + (uint32_t)st * 10240 + (r * 20 + q * 4) * 4, gp, ok ? 16 : 0);
        }
        #pragma unroll
        for (int rep = 0; rep < 2; rep++) {
            int i = tid + rep * 256;
            int r = i >> 2, q = i & 3;
            const void* gp = &g_w1p[((long)(2 * C + (q >> 1)) * 512 + om + r) * 8 + (q & 1) * 4];
            cpasync16(bs_base + (uint32_t)st * 10240 + (r * 20 + q * 4) * 4, gp, 16);
        }
    };

    fill(0, 0);
    CP_COMMIT();

    for (int C = 0; C < 32; C++) {
        int st = C & 1;
        if (C + 1 < 32) {
            fill(st ^ 1, C + 1);
            CP_COMMIT();
            CP_WAIT1();
        } else {
            CP_WAIT0();
        }
        __syncthreads();

        uint32_t soff = (uint32_t)st * 10240;
        #pragma unroll
        for (int kh = 0; kh < 2; kh++) {
            uint32_t koff = soff + (uint32_t)kh * 32;   // +8 words per k-half
            uint32_t ah[2][4];
            ldsm4(ah[0], aA[0] + koff);
            ldsm4(ah[1], aA[1] + koff);
            #pragma unroll
            for (int g = 0; g < 4; g++) {
                uint32_t bh[4];
                ldsm4(bh, aB[g] + koff);
                #pragma unroll
                for (int mt = 0; mt < 2; mt++) {
                    mma16816h(acc[mt][2 * g],     ah[mt], &bh[0]);
                    mma16816h(acc[mt][2 * g + 1], ah[mt], &bh[2]);
                }
            }
        }
        __syncthreads();
    }

    // epilogue: bn2+relu, round to fp16, store g_h2i
    #pragma unroll
    for (int mt = 0; mt < 2; mt++) {
        #pragma unroll
        for (int hf = 0; hf < 2; hf++) {
            int t = t0 + wt * 32 + mt * 16 + (lane >> 2) + hf * 8;
            if (t >= TT) continue;
            long tb = ((long)b * TT + t) * 256;
            #pragma unroll
            for (int n8 = 0; n8 < 8; n8++) {
                int ol = wo * 64 + n8 * 8 + 2 * (lane & 3);
                float v0 = fmaxf(fmaf(acc[mt][n8][hf * 2],     bn2s[ol],     bn2s[128 + ol]), 0.f);
                float v1 = fmaxf(fmaf(acc[mt][n8][hf * 2 + 1], bn2s[ol + 1], bn2s[129 + ol]), 0.f);
                int o = om + ol;
                g_h2i[tb + (long)(o >> 4) * 8 + ((o & 15) >> 1)] =
                    pack2h(__float2half_rn(v0), __float2half_rn(v1));
            }
        }
    }
}

// ---------------------------------------------------------------------------
// Conv: 3-branch dilated conv, pure fp16 MMA, 2-stage cp.async.  (R13 exact)
// Block 96t x 128o, 384 threads (12 warps: 3t x 4o), warp 32t x 32o.
// Epilogue: passes 0-2 store fp16 branches (smem-staged); pass 3 raw moments.
// ---------------------------------------------------------------------------
#define CSTG_WORDS 15048
#define CSM_BYTES  (2 * CSTG_WORDS * 4)

__global__ __launch_bounds__(384, 1)
void conv_mma_kernel()
{
    extern __shared__ uint32_t cs[];
    float* so = reinterpret_cast<float*>(cs);

    const int t0 = blockIdx.x * 96;
    const int om = blockIdx.y * 128;
    const int b  = blockIdx.z;

    const int tid  = threadIdx.x;
    const int warp = tid >> 5, lane = tid & 31;
    const int tsub = (warp >> 2) * 32;
    const int osub = (warp & 3) * 32;

    float acc[3][2][4][4];
    #pragma unroll
    for (int i = 0; i < 3; i++)
        #pragma unroll
        for (int m = 0; m < 2; m++)
            #pragma unroll
            for (int n = 0; n < 4; n++)
                #pragma unroll
                for (int j = 0; j < 4; j++) acc[i][m][n][j] = 0.f;

    const uint32_t cs_base  = saddr(cs);
    const uint32_t ws_base  = cs_base;
    const uint32_t hsp_base = cs_base + 13824 * 4;
    const int lrA = lane & 15, lwA = ((lane >> 4) & 1) * 4;
    const uint32_t aAbase = hsp_base + ((uint32_t)(tsub + lrA) * 12 + lwA) * 4;
    const int rB = ((lane >> 4) & 1) * 8 + (lane & 7);
    const int wB = ((lane >> 3) & 1) * 4;
    const uint32_t aB0 = ws_base + ((uint32_t)(osub + rB) * 12 + wB) * 4;

    auto fill = [&](int st, int ch) {
        uint32_t sb = (uint32_t)st * (CSTG_WORDS * 4);
        for (int i = tid; i < 2304; i += 384) {
            int comb = i >> 8;
            int r = i & 255;
            int o = r >> 1, q = r & 1;
            const void* gp = &g_wcp[(((long)comb * 32 + ch) * 512 + om + o) * 8 + q * 4];
            cpasync16(ws_base + sb + (uint32_t)(comb * 1536 + o * 12 + q * 4) * 4, gp, 16);
        }
        if (tid < 204) {
            int r = tid >> 1, q = tid & 1;
            int t = t0 - 3 + r;
            int ok = (t >= 0 && t < TT);
            const void* gp = &g_h2i[(((long)b * TT + (ok ? t : 0)) * 32 + ch) * 8 + q * 4];
            cpasync16(hsp_base + sb + (uint32_t)(r * 12 + q * 4) * 4, gp, ok ? 16 : 0);
        }
    };

    auto domma = [&](uint32_t soff, int comb, int br, uint32_t ah[2][4]) {
        #pragma unroll
        for (int g = 0; g < 2; g++) {
            uint32_t bh[4];
            ldsm4(bh, aB0 + soff + (uint32_t)(comb * 6144 + g * 768));
            #pragma unroll
            for (int mg = 0; mg < 2; mg++) {
                mma16816h(acc[br][mg][2 * g],     ah[mg], &bh[0]);
                mma16816h(acc[br][mg][2 * g + 1], ah[mg], &bh[2]);
            }
        }
    };

    fill(0, 0);
    CP_COMMIT();

    for (int ch = 0; ch < 32; ch++) {
        int st = ch & 1;
        if (ch + 1 < 32) {
            fill(st ^ 1, ch + 1);
            CP_COMMIT();
            CP_WAIT1();
        } else {
            CP_WAIT0();
        }
        __syncthreads();

        uint32_t soff = (uint32_t)st * (CSTG_WORDS * 4);
        uint32_t ah[2][4];

        {
            #pragma unroll
            for (int mg = 0; mg < 2; mg++)
                ldsm4(ah[mg], aAbase + soff + (uint32_t)(mg * 16 + 3) * 48);
            domma(soff, 1, 0, ah);
            domma(soff, 4, 1, ah);
            domma(soff, 7, 2, ah);
        }
        {
            const int combs[6] = {0, 2, 3, 5, 6, 8};
            const int doffs[6] = {2, 4, 1, 5, 0, 6};
            #pragma unroll
            for (int j = 0; j < 6; j++) {
                #pragma unroll
                for (int mg = 0; mg < 2; mg++)
                    ldsm4(ah[mg], aAbase + soff + (uint32_t)(mg * 16 + doffs[j]) * 48);
                domma(soff, combs[j], combs[j] / 3, ah);
            }
        }
        __syncthreads();
    }

    // epilogue: passes 0-2 = fp16 branch stores; pass 3 = branch-sum raw moments.
    const int tmax = (TT - t0 < 96) ? (TT - t0) : 96;
    #pragma unroll
    for (int p = 0; p < 4; p++) {
        __syncthreads();
        #pragma unroll
        for (int mg = 0; mg < 2; mg++) {
            #pragma unroll
            for (int n8 = 0; n8 < 4; n8++) {
                float d0, d1, d2, d3;
                if (p < 3) {
                    d0 = acc[p][mg][n8][0]; d1 = acc[p][mg][n8][1];
                    d2 = acc[p][mg][n8][2]; d3 = acc[p][mg][n8][3];
                } else {
                    d0 = acc[0][mg][n8][0] + acc[1][mg][n8][0] + acc[2][mg][n8][0];
                    d1 = acc[0][mg][n8][1] + acc[1][mg][n8][1] + acc[2][mg][n8][1];
                    d2 = acc[0][mg][n8][2] + acc[1][mg][n8][2] + acc[2][mg][n8][2];
                    d3 = acc[0][mg][n8][3] + acc[1][mg][n8][3] + acc[2][mg][n8][3];
                }
                int o = osub + n8 * 8 + 2 * (lane & 3);
                int t = tsub + mg * 16 + (lane >> 2);
                so[o * 100 + t]           = d0;
                so[(o + 1) * 100 + t]     = d1;
                so[o * 100 + t + 8]       = d2;
                so[(o + 1) * 100 + t + 8] = d3;
            }
        }
        __syncthreads();
        if (p < 3) {
            for (int i = tid; i < 3072; i += 384) {
                int o  = i / 24;
                int t4 = i - o * 24;
                int t = t0 + t4 * 4;
                if (t < TT) {
                    float4 v = *reinterpret_cast<const float4*>(&so[o * 100 + t4 * 4]);
                    long row = ((long)b * OUTC + om + o) * TT + t;
                    uint32_t w0 = pack2h(__float2half_rn(v.x), __float2half_rn(v.y));
                    uint32_t w1 = pack2h(__float2half_rn(v.z), __float2half_rn(v.w));
                    *reinterpret_cast<uint2*>(&g_fh[((long)p * FSZ + row) >> 1]) =
                        make_uint2(w0, w1);
                }
            }
        } else if (tid < 128) {
            int o = tid;
            float s1 = 0.f, s2 = 0.f, s3 = 0.f, s4 = 0.f;
            for (int t = 0; t < tmax; t++) {
                float v = so[o * 100 + t], v2 = v * v;
                s1 += v; s2 += v2; s3 += v2 * v; s4 += v2 * v2;
            }
            int idx = b * OUTC + om + o;
            atomicAdd(&g_mom[idx],                 s1);
            atomicAdd(&g_mom[BB * OUTC + idx],     s2);
            atomicAdd(&g_mom[2 * BB * OUTC + idx], s3);
            atomicAdd(&g_mom[3 * BB * OUTC + idx], s4);
        }
    }
}

// ---------------------------------------------------------------------------
// Kernel: finalize stats from raw moments
// ---------------------------------------------------------------------------
__global__ __launch_bounds__(256)
void stats_final_kernel()
{
    int idx = blockIdx.x * 256 + threadIdx.x;
    if (idx >= BB * OUTC) return;
    float r1 = g_mom[idx];
    float r2 = g_mom[BB * OUTC + idx];
    float r3 = g_mom[2 * BB * OUTC + idx];
    float r4 = g_mom[3 * BB * OUTC + idx];
    const float n = (float)TT;
    float m   = r1 / n;
    float ex2 = r2 / n, ex3 = r3 / n, ex4 = r4 / n;
    float var = (r2 - n * m * m) / (n - 1.0f);
    var = fmaxf(var, 0.f);
    float sd = sqrtf(var);
    float sc = fmaxf(sd, 0.01f);
    float m2 = m * m;
    float m3c = ex3 - 3.f * m * ex2 + 2.f * m * m2;
    float m4c = ex4 - 4.f * m * ex3 + 6.f * m2 * ex2 - 3.f * m2 * m2;
    int b = idx >> 9, o = idx & 511;
    float* st = g_stats + (long)b * (4 * OUTC);
    st[o]            = m;
    st[OUTC + o]     = sd;
    st[2 * OUTC + o] = m3c / (sc * sc * sc);
    st[3 * OUTC + o] = m4c / (sc * sc * sc * sc);
}

// ---------------------------------------------------------------------------
// Kernel: selection MLP + softmax -> g_s
// ---------------------------------------------------------------------------
__global__ __launch_bounds__(512)
void select_kernel(const float* __restrict__ sel_W1, const float* __restrict__ sel_b1,
                   const float* __restrict__ sel_W2, const float* __restrict__ sel_b2)
{
    const int b = blockIdx.x;
    const int tid = threadIdx.x;
    const int warp = tid >> 5, lane = tid & 31;

    __shared__ float sstats[4 * OUTC];
    __shared__ float sz[OUTC];
    __shared__ float ssv[NBR * OUTC];

    for (int i = tid; i < 4 * OUTC; i += 512)
        sstats[i] = g_stats[(long)b * (4 * OUTC) + i];
    __syncthreads();

    for (int r = warp; r < OUTC; r += 16) {
        float p = 0.f;
        for (int c = lane; c < 4 * OUTC; c += 32)
            p = fmaf(sel_W1[(long)r * (4 * OUTC) + c], sstats[c], p);
        p += __shfl_xor_sync(0xffffffff, p, 16);
        p += __shfl_xor_sync(0xffffffff, p, 8);
        p += __shfl_xor_sync(0xffffffff, p, 4);
        p += __shfl_xor_sync(0xffffffff, p, 2);
        p += __shfl_xor_sync(0xffffffff, p, 1);
        if (lane == 0) sz[r] = p + sel_b1[r];
    }
    __syncthreads();

    for (int idx = warp; idx < NBR * OUTC; idx += 16) {
        float p = 0.f;
        for (int c = lane; c < OUTC; c += 32)
            p = fmaf(sel_W2[(long)idx * OUTC + c], sz[c], p);
        p += __shfl_xor_sync(0xffffffff, p, 16);
        p += __shfl_xor_sync(0xffffffff, p, 8);
        p += __shfl_xor_sync(0xffffffff, p, 4);
        p += __shfl_xor_sync(0xffffffff, p, 2);
        p += __shfl_xor_sync(0xffffffff, p, 1);
        if (lane == 0) ssv[idx] = p + sel_b2[idx];
    }
    __syncthreads();

    if (tid < OUTC) {
        float v0 = ssv[tid], v1 = ssv[OUTC + tid], v2 = ssv[2 * OUTC + tid];
        float mx = fmaxf(v0, fmaxf(v1, v2));
        float e0 = __expf(v0 - mx), e1 = __expf(v1 - mx), e2 = __expf(v2 - mx);
        float inv = 1.f / (e0 + e1 + e2);
        float* sp = g_s + (long)b * (NBR * OUTC);
        sp[tid]            = e0 * inv;
        sp[OUTC + tid]     = e1 * inv;
        sp[2 * OUTC + tid] = e2 * inv;
    }
}

// ---------------------------------------------------------------------------
// Kernel: out[b,o,t] = sum_i s[b,i,o] * f[i,b,o,t]  (f in fp16, t-major)
// ---------------------------------------------------------------------------
__global__ __launch_bounds__(256)
void combine_kernel(float* __restrict__ out)
{
    const int idx = blockIdx.x * 256 + threadIdx.x;
    const int bo = idx / (TT / 4);
    const int t4 = idx - bo * (TT / 4);
    const int b = bo >> 9, o = bo & 511;

    const float* sp = g_s + (long)b * (NBR * OUTC);
    float s0 = sp[o], s1 = sp[OUTC + o], s2 = sp[2 * OUTC + o];

    const long base = (long)bo * TT + t4 * 4;
    uint2 u0 = *reinterpret_cast<const uint2*>(&g_fh[base >> 1]);
    uint2 u1 = *reinterpret_cast<const uint2*>(&g_fh[((long)FSZ + base) >> 1]);
    uint2 u2 = *reinterpret_cast<const uint2*>(&g_fh[(2L * FSZ + base) >> 1]);

    float2 a0 = __half22float2(*reinterpret_cast<__half2*>(&u0.x));
    float2 a1 = __half22float2(*reinterpret_cast<__half2*>(&u0.y));
    float2 b0 = __half22float2(*reinterpret_cast<__half2*>(&u1.x));
    float2 b1 = __half22float2(*reinterpret_cast<__half2*>(&u1.y));
    float2 c0 = __half22float2(*reinterpret_cast<__half2*>(&u2.x));
    float2 c1 = __half22float2(*reinterpret_cast<__half2*>(&u2.y));

    float4 r;
    r.x = s0 * a0.x + s1 * b0.x + s2 * c0.x;
    r.y = s0 * a0.y + s1 * b0.y + s2 * c0.y;
    r.z = s0 * a1.x + s1 * b1.x + s2 * c1.x;
    r.w = s0 * a1.y + s1 * b1.y + s2 * c1.y;
    *reinterpret_cast<float4*>(out + base) = r;
}

// ---------------------------------------------------------------------------
extern "C" void kernel_launch(void* const* d_in, const int* in_sizes, int n_in,
                              void* d_out, int out_size)
{
    const float* x         = (const float*)d_in[0];
    const float* bn1_gamma = (const float*)d_in[1];
    const float* bn1_beta  = (const float*)d_in[2];
    const float* bn1_mean  = (const float*)d_in[3];
    const float* bn1_var   = (const float*)d_in[4];
    const float* W1        = (const float*)d_in[5];
    const float* bn2_gamma = (const float*)d_in[6];
    const float* bn2_beta  = (const float*)d_in[7];
    const float* bn2_mean  = (const float*)d_in[8];
    const float* bn2_var   = (const float*)d_in[9];
    const float* conv_w    = (const float*)d_in[10];
    const float* sel_W1    = (const float*)d_in[11];
    const float* sel_b1    = (const float*)d_in[12];
    const float* sel_W2    = (const float*)d_in[13];
    const float* sel_b2    = (const float*)d_in[14];
    float* out = (float*)d_out;

    cudaFuncSetAttribute(conv_mma_kernel,
                         cudaFuncAttributeMaxDynamicSharedMemorySize, CSM_BYTES);

    prep_bn_kernel<<<1, 1024>>>(bn1_gamma, bn1_beta, bn1_mean, bn1_var,
                                bn2_gamma, bn2_beta, bn2_mean, bn2_var);
    prep_w1_kernel<<<(512 * 512 + 255) / 256, 256>>>(W1);
    prep_wc_kernel<<<(9 * 512 * 256 + 255) / 256, 256>>>(conv_w);
    {
        dim3 g(32, 16, BB);
        prep_x_kernel<<<g, 256>>>(x);
    }
    {
        dim3 g(16, 4, BB);
        gemm_mma_kernel<<<g, 256>>>();
    }
    {
        dim3 g((TT + 95) / 96, 4, BB);   // 21 x 4 x 16
        conv_mma_kernel<<<g, 384, CSM_BYTES>>>();
    }
    stats_final_kernel<<<(BB * OUTC + 255) / 256, 256>>>();
    select_kernel<<<BB, 512>>>(sel_W1, sel_b1, sel_W2, sel_b2);
    combine_kernel<<<(BB * OUTC * TT / 4 + 255) / 256, 256>>>(out);
}